// round 13
// baseline (speedup 1.0000x reference)
#include <cuda_runtime.h>
#include <cuda_pipeline.h>
#include <cuda_bf16.h>
#include <cstdint>

#define N_NODES 50000
#define N_EDGES 800000
#define M_TILES 391   // ceil(50000/128)

// ---------------- static device scratch ----------------
__device__ float g_qkvs[(size_t)N_NODES * 544];        // q|k|v|skip|qE strided rows
__device__ __nv_bfloat16 g_Ahl[(size_t)N_NODES * 256]; // activations hi|lo (bf16)
__device__ __nv_bfloat16 g_WT[544 * 256];              // W~^T per layer: [NT][2K] hi|lo
__device__ float g_ball[544];                          // concat bias per layer
__device__ float g_hA[(size_t)N_NODES * 128];
__device__ float g_hB[(size_t)N_NODES * 128];
__device__ float g_aw[(size_t)N_NODES * 32];
__device__ float g_ea[(size_t)N_EDGES * 32];
__device__ float g_Wqe[128 * 32];
__device__ float g_bqe[32];
__device__ int   g_src[N_EDGES];
__device__ int   g_dst[N_EDGES];
__device__ int   g_esrc[N_EDGES];
__device__ int   g_rowptr[N_NODES + 1];
__device__ int   g_cnt[N_NODES];
__device__ int   g_wofs[N_NODES];
__device__ int   g_bsum[64];
__device__ int   g_boff[64];
__device__ int   g_flag[1];

// ---------------- packed fp32x2 helpers ----------------
__device__ __forceinline__ unsigned long long pk2(float x, float y) {
    unsigned long long r;
    asm("mov.b64 %0, {%1,%2};" : "=l"(r) : "f"(x), "f"(y));
    return r;
}
__device__ __forceinline__ void upk2(unsigned long long p, float& x, float& y) {
    asm("mov.b64 {%0,%1}, %2;" : "=f"(x), "=f"(y) : "l"(p));
}
__device__ __forceinline__ unsigned long long fma2(unsigned long long a, unsigned long long b,
                                                   unsigned long long c) {
    unsigned long long d;
    asm("fma.rn.f32x2 %0, %1, %2, %3;" : "=l"(d) : "l"(a), "l"(b), "l"(c));
    return d;
}

__device__ __forceinline__ uint32_t smem_to_u32(const void* p) {
    uint32_t a;
    asm("{ .reg .u64 t; cvta.to.shared.u64 t, %1; cvt.u32.u64 %0, t; }" : "=r"(a) : "l"(p));
    return a;
}

// ---------------- HMMA helpers (baseline PTX, sm_80+) ----------------
__device__ __forceinline__ void ldsm4(uint32_t* r, uint32_t addr) {
    asm volatile("ldmatrix.sync.aligned.m8n8.x4.shared.b16 {%0,%1,%2,%3}, [%4];"
                 : "=r"(r[0]), "=r"(r[1]), "=r"(r[2]), "=r"(r[3]) : "r"(addr));
}
__device__ __forceinline__ void mma16816(float* c, const uint32_t* a, const uint32_t* b) {
    asm volatile("mma.sync.aligned.m16n8k16.row.col.f32.bf16.bf16.f32 "
                 "{%0,%1,%2,%3}, {%4,%5,%6,%7}, {%8,%9}, {%0,%1,%2,%3};"
                 : "+f"(c[0]), "+f"(c[1]), "+f"(c[2]), "+f"(c[3])
                 : "r"(a[0]), "r"(a[1]), "r"(a[2]), "r"(a[3]), "r"(b[0]), "r"(b[1]));
}

// ---------------- edge_index dtype detection ----------------
__global__ void detect_kernel(const void* ei) {
    __shared__ int ok;
    if (threadIdx.x == 0) ok = 1;
    __syncthreads();
    const long long* p = (const long long*)ei;
    long long v = p[threadIdx.x];
    if (!(v >= 0 && v < (long long)N_NODES)) atomicExch(&ok, 0);
    __syncthreads();
    if (threadIdx.x == 0) g_flag[0] = ok;
}

__global__ void convert_kernel(const void* ei) {
    int i = blockIdx.x * blockDim.x + threadIdx.x;
    int is64 = g_flag[0];
    if (i < N_EDGES) {
        int s, d;
        if (is64) {
            const long long* p = (const long long*)ei;
            s = (int)p[i]; d = (int)p[N_EDGES + i];
        } else {
            const int* p = (const int*)ei;
            s = p[i]; d = p[N_EDGES + i];
        }
        g_src[i] = s; g_dst[i] = d;
    }
    if (i < N_NODES) g_cnt[i] = 0;
}

__global__ void hist_kernel() {
    int i = blockIdx.x * blockDim.x + threadIdx.x;
    if (i < N_EDGES) atomicAdd(&g_cnt[g_dst[i]], 1);
}

__global__ void scanA_kernel() {
    __shared__ int wsum[32];
    int tid = threadIdx.x, lane = tid & 31, wid = tid >> 5;
    int i = blockIdx.x * 1024 + tid;
    int v = (i < N_NODES) ? g_cnt[i] : 0;
    int x = v;
    #pragma unroll
    for (int off = 1; off < 32; off <<= 1) {
        int t = __shfl_up_sync(0xffffffffu, x, off);
        if (lane >= off) x += t;
    }
    if (lane == 31) wsum[wid] = x;
    __syncthreads();
    if (wid == 0) {
        int y = wsum[lane];
        #pragma unroll
        for (int off = 1; off < 32; off <<= 1) {
            int t = __shfl_up_sync(0xffffffffu, y, off);
            if (lane >= off) y += t;
        }
        wsum[lane] = y;
    }
    __syncthreads();
    int incl = x + (wid ? wsum[wid - 1] : 0);
    if (i < N_NODES) g_rowptr[i + 1] = incl;
    if (tid == 1023) g_bsum[blockIdx.x] = incl;
}

__global__ void scanB_kernel(int nb) {
    __shared__ int w0tot;
    int tid = threadIdx.x, lane = tid & 31, wid = tid >> 5;
    int v = (tid < nb) ? g_bsum[tid] : 0;
    int x = v;
    #pragma unroll
    for (int off = 1; off < 32; off <<= 1) {
        int t = __shfl_up_sync(0xffffffffu, x, off);
        if (lane >= off) x += t;
    }
    if (wid == 0 && lane == 31) w0tot = x;
    __syncthreads();
    int incl = x + (wid ? w0tot : 0);
    g_boff[tid] = incl - v;
    if (tid == 0) g_rowptr[0] = 0;
}

__global__ void scanC_kernel() {
    int i = blockIdx.x * 1024 + threadIdx.x;
    if (i < N_NODES) {
        int off = g_boff[blockIdx.x];
        int r = g_rowptr[i + 1] + off;
        g_rowptr[i + 1] = r;
        g_wofs[i] = r - g_cnt[i];
    }
}

__global__ void scatter_kernel(const float* __restrict__ ea) {
    int w = (blockIdx.x * blockDim.x + threadIdx.x) >> 5;
    int lane = threadIdx.x & 31;
    if (w >= N_EDGES) return;
    int pos = 0;
    if (lane == 0) {
        int d = g_dst[w];
        pos = atomicAdd(&g_wofs[d], 1);
        g_esrc[pos] = g_src[w];
    }
    pos = __shfl_sync(0xffffffffu, pos, 0);
    g_ea[(size_t)pos * 32 + lane] = ea[(size_t)w * 32 + lane];
}

// ---------------- hi/lo bf16 split ----------------
__device__ __forceinline__ void splitf(float x, __nv_bfloat16& hi, __nv_bfloat16& lo) {
    hi = __float2bfloat16(x);
    lo = __float2bfloat16(x - __bfloat162float(hi));
}

// activations: X[M,K] fp32 -> Ahl[M,2K] bf16 (hi cols [0,K), lo cols [K,2K))
__global__ void cvt_kernel(const float* __restrict__ X, int M, int K) {
    int i = blockIdx.x * 256 + threadIdx.x;
    if (i >= M * K) return;
    int r = i / K, c = i % K;
    __nv_bfloat16 hi, lo;
    splitf(X[i], hi, lo);
    g_Ahl[(size_t)r * 2 * K + c] = hi;
    g_Ahl[(size_t)r * 2 * K + K + c] = lo;
}

// ---------------- composite weights: Wqe = Wq @ We^T, bqe = bq @ We^T ----------------
__global__ void compose_kernel(const float* __restrict__ Wq, const float* __restrict__ bq,
                               const float* __restrict__ We, int K, int D) {
    int idx = blockIdx.x * 256 + threadIdx.x;
    if (idx < K * 32) {
        int kk = idx >> 5, n = idx & 31;
        float s = 0.f;
        for (int j = 0; j < D; j++) s = fmaf(Wq[kk * D + j], We[n * D + j], s);
        g_Wqe[idx] = s;
    }
    if (idx < 32) {
        float s = 0.f;
        for (int j = 0; j < D; j++) s = fmaf(bq[j], We[idx * D + j], s);
        g_bqe[idx] = s;
    }
}

// ---------------- weight prep: WT[NT][2K] bf16 (hi|lo), ball[NT] ----------------
__global__ void wprep_kernel(const float* __restrict__ Wq, const float* __restrict__ Wk,
                             const float* __restrict__ Wv, const float* __restrict__ Ws,
                             const float* __restrict__ bq, const float* __restrict__ bk,
                             const float* __restrict__ bv, const float* __restrict__ bs,
                             int K, int D, int NT) {
    int idx = blockIdx.x * 256 + threadIdx.x;
    if (idx >= NT * K) return;
    int n = idx / K, kk = idx % K;
    float w;
    if (n < D)            w = Wq[kk * D + n];
    else if (n < 2 * D)   w = Wk[kk * D + (n - D)];
    else if (n < 3 * D)   w = Wv[kk * D + (n - 2 * D)];
    else if (n < 4 * D)   w = Ws[kk * D + (n - 3 * D)];
    else                  w = g_Wqe[kk * 32 + (n - 4 * D)];
    __nv_bfloat16 hi, lo;
    splitf(w, hi, lo);
    g_WT[(size_t)n * 2 * K + kk] = hi;
    g_WT[(size_t)n * 2 * K + K + kk] = lo;
    if (kk == 0) {
        float b;
        if (n < D)          b = bq[n];
        else if (n < 2 * D) b = bk[n - D];
        else if (n < 3 * D) b = bv[n - 2 * D];
        else if (n < 4 * D) b = bs[n - 3 * D];
        else                b = g_bqe[n - 4 * D];
        g_ball[n] = b;
    }
}

// ---------------- HMMA GEMM: qkvs[M, NT] = Ahl~ @ WT~^T + ball ----------------
// K' = 3K: chunks of 64 over [A_hi*W_hi | A_hi*W_lo | A_lo*W_hi].
// Block 256 thr (8 warps, 4x2), tile 128x64, warp tile 32x32, m16n8k16 bf16 HMMA.
#define APAD 72   // padded row length (bf16 elems): 144 B stride -> conflict-free ldmatrix
__global__ __launch_bounds__(256) void gemm_mma(int M, int K, int NT) {
    __shared__ __align__(16) __nv_bfloat16 As[2][128][APAD];
    __shared__ __align__(16) __nv_bfloat16 Bs[2][64][APAD];
    int tid = threadIdx.x, lane = tid & 31, wid = tid >> 5;
    int warp_m = wid & 3, warp_n = wid >> 2;
    int m0 = blockIdx.x * 128, n0 = blockIdx.y * 64;
    int K2 = 2 * K;
    int NC = 3 * K / 64;

    const __nv_bfloat16* Ahl = g_Ahl;
    const __nv_bfloat16* WT = g_WT;

    float cfr[2][4][4];
    #pragma unroll
    for (int mt = 0; mt < 2; mt++)
        #pragma unroll
        for (int nt = 0; nt < 4; nt++)
            #pragma unroll
            for (int j = 0; j < 4; j++) cfr[mt][nt][j] = 0.f;

    auto stage = [&](int c, int buf) {
        int kp = c * 64;
        int ac = (kp < K) ? kp : kp - K;          // A: [hi | hi | lo]
        int bc = (kp < 2 * K) ? kp : kp - 2 * K;  // B: [hi | lo | hi]
        #pragma unroll
        for (int f = tid; f < 1024; f += 256) {
            int r = f >> 3, c16 = f & 7;
            int gr = m0 + r;
            if (gr < M)
                __pipeline_memcpy_async(&As[buf][r][c16 * 8],
                                        &Ahl[(size_t)gr * K2 + ac + c16 * 8], 16);
        }
        #pragma unroll
        for (int f = tid; f < 512; f += 256) {
            int r = f >> 3, c16 = f & 7;
            int n = n0 + r;
            if (n < NT)
                __pipeline_memcpy_async(&Bs[buf][r][c16 * 8],
                                        &WT[(size_t)n * K2 + bc + c16 * 8], 16);
        }
        __pipeline_commit();
    };

    stage(0, 0);

    for (int c = 0; c < NC; c++) {
        int buf = c & 1;
        bool more = (c + 1 < NC);
        if (more) stage(c + 1, buf ^ 1);
        __pipeline_wait_prior(more ? 1 : 0);
        __syncthreads();

        uint32_t sA = smem_to_u32(&As[buf][0][0]);
        uint32_t sB = smem_to_u32(&Bs[buf][0][0]);
        #pragma unroll
        for (int kk = 0; kk < 64; kk += 16) {
            uint32_t afr[2][4], bfr[2][4];
            #pragma unroll
            for (int mt = 0; mt < 2; mt++) {
                int row = warp_m * 32 + mt * 16 + (lane & 15);
                int koff = kk + ((lane >> 4) << 3);
                ldsm4(afr[mt], sA + row * (APAD * 2) + koff * 2);
            }
            #pragma unroll
            for (int ntp = 0; ntp < 2; ntp++) {
                int nrow = warp_n * 32 + ntp * 16 + ((lane >> 4) << 3) + (lane & 7);
                int koff = kk + (((lane >> 3) & 1) << 3);
                ldsm4(bfr[ntp], sB + nrow * (APAD * 2) + koff * 2);
            }
            #pragma unroll
            for (int mt = 0; mt < 2; mt++)
                #pragma unroll
                for (int nt = 0; nt < 4; nt++)
                    mma16816(cfr[mt][nt], afr[mt], &bfr[nt >> 1][(nt & 1) * 2]);
        }
        __syncthreads();
    }

    // epilogue
    int g = lane >> 2, t4 = lane & 3;
    float* out = g_qkvs;
    #pragma unroll
    for (int mt = 0; mt < 2; mt++) {
        #pragma unroll
        for (int nt = 0; nt < 4; nt++) {
            int col = n0 + warp_n * 32 + nt * 8 + t4 * 2;
            if (col >= NT) continue;
            float2 bb = *(const float2*)&g_ball[col];
            int r0 = m0 + warp_m * 32 + mt * 16 + g;
            if (r0 < M) {
                float2 o = make_float2(cfr[mt][nt][0] + bb.x, cfr[mt][nt][1] + bb.y);
                *(float2*)&out[(size_t)r0 * NT + col] = o;
            }
            int r1 = r0 + 8;
            if (r1 < M) {
                float2 o = make_float2(cfr[mt][nt][2] + bb.x, cfr[mt][nt][3] + bb.y);
                *(float2*)&out[(size_t)r1 * NT + col] = o;
            }
        }
    }
}

// ---------------- attention: fused, strided qkvs ----------------
template <int DOUT>
__global__ void attn_kernel(const float* __restrict__ qkvs, int NT,
                            float* __restrict__ h, float* __restrict__ aw) {
    int w = (blockIdx.x * blockDim.x + threadIdx.x) >> 5;
    if (w >= N_NODES) return;
    int lane = threadIdx.x & 31;
    constexpr int VEC = DOUT / 32;
    float qr[VEC], acc[VEC];
    {
        const float* qp = qkvs + (size_t)w * NT + lane * VEC;
        #pragma unroll
        for (int j = 0; j < VEC; j++) { qr[j] = qp[j]; acc[j] = 0.f; }
    }
    float qe_l = qkvs[(size_t)w * NT + 4 * DOUT + lane];
    float m = -__int_as_float(0x7f800000);
    float s = 0.f, accw = 0.f;
    int beg = g_rowptr[w], end = g_rowptr[w + 1];
    const float scale = rsqrtf((float)DOUT);

    float kc[VEC], vc[VEC], eac = 0.f;
    if (beg < end) {
        int src = g_esrc[beg];
        eac = g_ea[(size_t)beg * 32 + lane];
        const float* kp = qkvs + (size_t)src * NT + DOUT + lane * VEC;
        const float* vp = qkvs + (size_t)src * NT + 2 * DOUT + lane * VEC;
        if constexpr (VEC == 4) {
            float4 kt = *(const float4*)kp; float4 vt = *(const float4*)vp;
            kc[0] = kt.x; kc[1] = kt.y; kc[2] = kt.z; kc[3] = kt.w;
            vc[0] = vt.x; vc[1] = vt.y; vc[2] = vt.z; vc[3] = vt.w;
        } else if constexpr (VEC == 2) {
            float2 kt = *(const float2*)kp; float2 vt = *(const float2*)vp;
            kc[0] = kt.x; kc[1] = kt.y; vc[0] = vt.x; vc[1] = vt.y;
        } else { kc[0] = kp[0]; vc[0] = vp[0]; }
    }
    for (int i = beg; i < end; i++) {
        float eav = eac;
        float kv[VEC], vv[VEC];
        #pragma unroll
        for (int j = 0; j < VEC; j++) { kv[j] = kc[j]; vv[j] = vc[j]; }
        if (i + 1 < end) {
            int src = g_esrc[i + 1];
            eac = g_ea[(size_t)(i + 1) * 32 + lane];
            const float* kp = qkvs + (size_t)src * NT + DOUT + lane * VEC;
            const float* vp = qkvs + (size_t)src * NT + 2 * DOUT + lane * VEC;
            if constexpr (VEC == 4) {
                float4 kt = *(const float4*)kp; float4 vt = *(const float4*)vp;
                kc[0] = kt.x; kc[1] = kt.y; kc[2] = kt.z; kc[3] = kt.w;
                vc[0] = vt.x; vc[1] = vt.y; vc[2] = vt.z; vc[3] = vt.w;
            } else if constexpr (VEC == 2) {
                float2 kt = *(const float2*)kp; float2 vt = *(const float2*)vp;
                kc[0] = kt.x; kc[1] = kt.y; vc[0] = vt.x; vc[1] = vt.y;
            } else { kc[0] = kp[0]; vc[0] = vp[0]; }
        }
        float dot = qe_l * eav;
        #pragma unroll
        for (int j = 0; j < VEC; j++) dot = fmaf(qr[j], kv[j], dot);
        #pragma unroll
        for (int off = 16; off; off >>= 1) dot += __shfl_xor_sync(0xffffffffu, dot, off);
        float alpha = dot * scale;
        float nm = fmaxf(m, alpha);
        float corr = __expf(m - nm);
        float wgt = __expf(alpha - nm);
        s = s * corr + wgt;
        accw = accw * corr + wgt * eav;
        #pragma unroll
        for (int j = 0; j < VEC; j++) acc[j] = fmaf(wgt, vv[j], acc[j] * corr);
        m = nm;
    }
    float inv = (s > 0.f) ? 1.f / s : 0.f;
    const float* sp = qkvs + (size_t)w * NT + 3 * DOUT + lane * VEC;
    float* hp = h + (size_t)w * DOUT + lane * VEC;
    #pragma unroll
    for (int j = 0; j < VEC; j++) hp[j] = sp[j] + acc[j] * inv;
    aw[(size_t)w * 32 + lane] = accw * inv;
}

// ---------------- agg fuse: H = relu(H + AW @ We); also writes bf16 hi/lo split ----------------
template <int BN>
__global__ __launch_bounds__(256) void aggfuse(const float* __restrict__ AW,
                                               const float* __restrict__ We,
                                               float* H, int M) {
    constexpr int BM = 128, BK = 32;
    constexpr int TN = BN / 16, TM = 8, NH = TN / 2;
    __shared__ float As[BK][BM + 4];
    __shared__ float Ws[BK][BN];
    int tid = threadIdx.x;
    int ct = tid & 15, rt = tid >> 4;
    int row0 = blockIdx.x * BM;

    #pragma unroll
    for (int it = 0; it < 4; it++) {
        int f = tid + 256 * it;
        int r = f >> 3, kq = f & 7;
        int gr = row0 + r;
        float4 a = make_float4(0.f, 0.f, 0.f, 0.f);
        if (gr < M) a = *(const float4*)&AW[(size_t)gr * 32 + kq * 4];
        As[kq * 4 + 0][r] = a.x;
        As[kq * 4 + 1][r] = a.y;
        As[kq * 4 + 2][r] = a.z;
        As[kq * 4 + 3][r] = a.w;
    }
    #pragma unroll
    for (int f = tid; f < 8 * BN; f += 256) {
        int kk = f / (BN / 4), n4 = f % (BN / 4);
        *(float4*)&Ws[kk][n4 * 4] = *(const float4*)&We[(size_t)kk * BN + n4 * 4];
    }
    __syncthreads();

    unsigned long long acc[TM][NH];
    #pragma unroll
    for (int t = 0; t < TM; t++)
        #pragma unroll
        for (int n = 0; n < NH; n++) acc[t][n] = 0ull;

    #pragma unroll
    for (int kk = 0; kk < BK; kk++) {
        float4 a0 = *(const float4*)&As[kk][rt * 8];
        float4 a1 = *(const float4*)&As[kk][rt * 8 + 4];
        float av[8] = {a0.x, a0.y, a0.z, a0.w, a1.x, a1.y, a1.z, a1.w};
        unsigned long long b2[NH];
        const float* wp = &Ws[kk][ct * TN];
        if constexpr (NH == 4) {
            ulonglong2 p0 = ((const ulonglong2*)wp)[0];
            ulonglong2 p1 = ((const ulonglong2*)wp)[1];
            b2[0] = p0.x; b2[1] = p0.y; b2[2] = p1.x; b2[3] = p1.y;
        } else if constexpr (NH == 2) {
            ulonglong2 p0 = ((const ulonglong2*)wp)[0];
            b2[0] = p0.x; b2[1] = p0.y;
        } else {
            b2[0] = *(const unsigned long long*)wp;
        }
        #pragma unroll
        for (int t = 0; t < TM; t++) {
            unsigned long long a2 = pk2(av[t], av[t]);
            #pragma unroll
            for (int n = 0; n < NH; n++) acc[t][n] = fma2(a2, b2[n], acc[t][n]);
        }
    }
    #pragma unroll
    for (int t = 0; t < TM; t++) {
        int r = row0 + rt * 8 + t;
        if (r < M) {
            #pragma unroll
            for (int n = 0; n < NH; n++) {
                float x, y; upk2(acc[t][n], x, y);
                float2 hprev = *(const float2*)&H[(size_t)r * BN + ct * TN + 2 * n];
                float2 o = make_float2(fmaxf(hprev.x + x, 0.f), fmaxf(hprev.y + y, 0.f));
                *(float2*)&H[(size_t)r * BN + ct * TN + 2 * n] = o;
                // fused hi/lo bf16 split for next layer's GEMM input
                int col = ct * TN + 2 * n;
                __nv_bfloat16 hx, lx, hy, ly;
                splitf(o.x, hx, lx);
                splitf(o.y, hy, ly);
                __nv_bfloat162* hi2 = (__nv_bfloat162*)&g_Ahl[(size_t)r * 2 * BN + col];
                __nv_bfloat162* lo2 = (__nv_bfloat162*)&g_Ahl[(size_t)r * 2 * BN + BN + col];
                *hi2 = __nv_bfloat162(hx, hy);
                *lo2 = __nv_bfloat162(lx, ly);
            }
        }
    }
}

// ---------------- final linear ----------------
__global__ void final_kernel(const float* __restrict__ h, const float* __restrict__ Wc,
                             const float* __restrict__ bc, float* __restrict__ out) {
    int i = blockIdx.x * blockDim.x + threadIdx.x;
    if (i >= N_NODES) return;
    float s = bc[0];
    #pragma unroll
    for (int c = 0; c < 32; c++) s = fmaf(h[(size_t)i * 32 + c], __ldg(&Wc[c]), s);
    out[i] = s;
}

// ---------------- host driver ----------------
extern "C" void kernel_launch(void* const* d_in, const int* in_sizes, int n_in,
                              void* d_out, int out_size) {
    const float* x  = (const float*)d_in[0];
    const void*  ei = d_in[1];
    const float* ea = (const float*)d_in[2];
    const float* W[3][9];
    int p = 3;
    for (int l = 0; l < 3; l++)
        for (int j = 0; j < 9; j++) W[l][j] = (const float*)d_in[p++];
    const float* Wc = (const float*)d_in[30];
    const float* bc = (const float*)d_in[31];

    float *hA, *hB, *awb, *qkvsb;
    cudaGetSymbolAddress((void**)&hA,    g_hA);
    cudaGetSymbolAddress((void**)&hB,    g_hB);
    cudaGetSymbolAddress((void**)&awb,   g_aw);
    cudaGetSymbolAddress((void**)&qkvsb, g_qkvs);

    int din[3]  = {128, 128, 64};
    int dout[3] = {128, 64, 32};
    float* houts[3] = {hA, hB, hA};
    dim3 ngrid((N_NODES * 32 + 255) / 256);
    int gx = (N_NODES + 127) / 128;

    // ---- Layer-1 GEMM path first (independent of graph preprocessing).
    // gemm_mma is launch #4 => captured by the profiler.
    cvt_kernel<<<(N_NODES * 128 + 255) / 256, 256>>>(x, N_NODES, 128);
    compose_kernel<<<(128 * 32 + 255) / 256, 256>>>(W[0][0], W[0][1], W[0][6], 128, 128);
    wprep_kernel<<<(544 * 128 + 255) / 256, 256>>>(W[0][0], W[0][2], W[0][4], W[0][7],
                                                   W[0][1], W[0][3], W[0][5], W[0][8],
                                                   128, 128, 544);
    gemm_mma<<<dim3(M_TILES, 9), 256>>>(N_NODES, 128, 544);

    // ---- graph preprocessing
    detect_kernel<<<1, 256>>>(ei);
    convert_kernel<<<(N_EDGES + 255) / 256, 256>>>(ei);
    hist_kernel<<<(N_EDGES + 255) / 256, 256>>>();
    int NB = (N_NODES + 1023) / 1024;
    scanA_kernel<<<NB, 1024>>>();
    scanB_kernel<<<1, 64>>>(NB);
    scanC_kernel<<<NB, 1024>>>();
    scatter_kernel<<<(N_EDGES * 32 + 255) / 256, 256>>>(ea);

    for (int l = 0; l < 3; l++) {
        int K = din[l], D = dout[l];
        int NT = 4 * D + 32;
        float* hout = houts[l];
        if (l > 0) {
            // Ahl for this layer was written by previous layer's aggfuse (fused split)
            compose_kernel<<<(K * 32 + 255) / 256, 256>>>(W[l][0], W[l][1], W[l][6], K, D);
            wprep_kernel<<<(NT * K + 255) / 256, 256>>>(W[l][0], W[l][2], W[l][4], W[l][7],
                                                        W[l][1], W[l][3], W[l][5], W[l][8],
                                                        K, D, NT);
            int ntiles = (NT + 63) / 64;
            gemm_mma<<<dim3(M_TILES, ntiles), 256>>>(N_NODES, K, NT);
        }
        if (D == 128)      attn_kernel<128><<<ngrid, 256>>>(qkvsb, NT, hout, awb);
        else if (D == 64)  attn_kernel<64><<<ngrid, 256>>>(qkvsb, NT, hout, awb);
        else               attn_kernel<32><<<ngrid, 256>>>(qkvsb, NT, hout, awb);
        if (D == 128)      aggfuse<128><<<gx, 256>>>(awb, W[l][6], hout, N_NODES);
        else if (D == 64)  aggfuse<64><<<gx, 256>>>(awb, W[l][6], hout, N_NODES);
        else               aggfuse<32><<<gx, 256>>>(awb, W[l][6], hout, N_NODES);
        hin_unused:;
        (void)0;
    }
    final_kernel<<<(N_NODES + 255) / 256, 256>>>(hA, Wc, bc, (float*)d_out);
}

// round 16
// speedup vs baseline: 1.0635x; 1.0635x over previous
#include <cuda_runtime.h>
#include <cuda_pipeline.h>
#include <cuda_bf16.h>
#include <cstdint>

#define N_NODES 50000
#define N_EDGES 800000
#define M_TILES 391   // ceil(50000/128)

// ---------------- static device scratch ----------------
__device__ float g_qse[(size_t)N_NODES * 288];         // q|skip|qE rows (2D+32)
__device__ float g_kv[(size_t)N_NODES * 256];          // k|v rows (2D) -- the ONLY gathered tensor
__device__ __nv_bfloat16 g_Ahl[(size_t)N_NODES * 256]; // activations hi|lo (bf16)
__device__ __nv_bfloat16 g_WT[544 * 256];              // W~^T per layer: [NT][2K] hi|lo
__device__ float g_ball[544];                          // concat bias per layer
__device__ float g_hA[(size_t)N_NODES * 128];
__device__ float g_hB[(size_t)N_NODES * 128];
__device__ float g_aw[(size_t)N_NODES * 32];
__device__ float g_ea[(size_t)N_EDGES * 32];
__device__ float g_Wqe[128 * 32];
__device__ float g_bqe[32];
__device__ int   g_src[N_EDGES];
__device__ int   g_dst[N_EDGES];
__device__ int   g_esrc[N_EDGES];
__device__ int   g_rowptr[N_NODES + 1];
__device__ int   g_cnt[N_NODES];
__device__ int   g_wofs[N_NODES];
__device__ int   g_bsum[64];
__device__ int   g_boff[64];
__device__ int   g_flag[1];

// ---------------- packed fp32x2 helpers ----------------
__device__ __forceinline__ unsigned long long pk2(float x, float y) {
    unsigned long long r;
    asm("mov.b64 %0, {%1,%2};" : "=l"(r) : "f"(x), "f"(y));
    return r;
}
__device__ __forceinline__ void upk2(unsigned long long p, float& x, float& y) {
    asm("mov.b64 {%0,%1}, %2;" : "=f"(x), "=f"(y) : "l"(p));
}
__device__ __forceinline__ unsigned long long fma2(unsigned long long a, unsigned long long b,
                                                   unsigned long long c) {
    unsigned long long d;
    asm("fma.rn.f32x2 %0, %1, %2, %3;" : "=l"(d) : "l"(a), "l"(b), "l"(c));
    return d;
}

__device__ __forceinline__ uint32_t smem_to_u32(const void* p) {
    uint32_t a;
    asm("{ .reg .u64 t; cvta.to.shared.u64 t, %1; cvt.u32.u64 %0, t; }" : "=r"(a) : "l"(p));
    return a;
}

// ---------------- HMMA helpers (baseline PTX, sm_80+) ----------------
__device__ __forceinline__ void ldsm4(uint32_t* r, uint32_t addr) {
    asm volatile("ldmatrix.sync.aligned.m8n8.x4.shared.b16 {%0,%1,%2,%3}, [%4];"
                 : "=r"(r[0]), "=r"(r[1]), "=r"(r[2]), "=r"(r[3]) : "r"(addr));
}
__device__ __forceinline__ void mma16816(float* c, const uint32_t* a, const uint32_t* b) {
    asm volatile("mma.sync.aligned.m16n8k16.row.col.f32.bf16.bf16.f32 "
                 "{%0,%1,%2,%3}, {%4,%5,%6,%7}, {%8,%9}, {%0,%1,%2,%3};"
                 : "+f"(c[0]), "+f"(c[1]), "+f"(c[2]), "+f"(c[3])
                 : "r"(a[0]), "r"(a[1]), "r"(a[2]), "r"(a[3]), "r"(b[0]), "r"(b[1]));
}

// ---------------- edge_index dtype detection ----------------
__global__ void detect_kernel(const void* ei) {
    __shared__ int ok;
    if (threadIdx.x == 0) ok = 1;
    __syncthreads();
    const long long* p = (const long long*)ei;
    long long v = p[threadIdx.x];
    if (!(v >= 0 && v < (long long)N_NODES)) atomicExch(&ok, 0);
    __syncthreads();
    if (threadIdx.x == 0) g_flag[0] = ok;
}

__global__ void convert_kernel(const void* ei) {
    int i = blockIdx.x * blockDim.x + threadIdx.x;
    int is64 = g_flag[0];
    if (i < N_EDGES) {
        int s, d;
        if (is64) {
            const long long* p = (const long long*)ei;
            s = (int)p[i]; d = (int)p[N_EDGES + i];
        } else {
            const int* p = (const int*)ei;
            s = p[i]; d = p[N_EDGES + i];
        }
        g_src[i] = s; g_dst[i] = d;
    }
    if (i < N_NODES) g_cnt[i] = 0;
}

__global__ void hist_kernel() {
    int i = blockIdx.x * blockDim.x + threadIdx.x;
    if (i < N_EDGES) atomicAdd(&g_cnt[g_dst[i]], 1);
}

__global__ void scanA_kernel() {
    __shared__ int wsum[32];
    int tid = threadIdx.x, lane = tid & 31, wid = tid >> 5;
    int i = blockIdx.x * 1024 + tid;
    int v = (i < N_NODES) ? g_cnt[i] : 0;
    int x = v;
    #pragma unroll
    for (int off = 1; off < 32; off <<= 1) {
        int t = __shfl_up_sync(0xffffffffu, x, off);
        if (lane >= off) x += t;
    }
    if (lane == 31) wsum[wid] = x;
    __syncthreads();
    if (wid == 0) {
        int y = wsum[lane];
        #pragma unroll
        for (int off = 1; off < 32; off <<= 1) {
            int t = __shfl_up_sync(0xffffffffu, y, off);
            if (lane >= off) y += t;
        }
        wsum[lane] = y;
    }
    __syncthreads();
    int incl = x + (wid ? wsum[wid - 1] : 0);
    if (i < N_NODES) g_rowptr[i + 1] = incl;
    if (tid == 1023) g_bsum[blockIdx.x] = incl;
}

__global__ void scanB_kernel(int nb) {
    __shared__ int w0tot;
    int tid = threadIdx.x, lane = tid & 31, wid = tid >> 5;
    int v = (tid < nb) ? g_bsum[tid] : 0;
    int x = v;
    #pragma unroll
    for (int off = 1; off < 32; off <<= 1) {
        int t = __shfl_up_sync(0xffffffffu, x, off);
        if (lane >= off) x += t;
    }
    if (wid == 0 && lane == 31) w0tot = x;
    __syncthreads();
    int incl = x + (wid ? w0tot : 0);
    g_boff[tid] = incl - v;
    if (tid == 0) g_rowptr[0] = 0;
}

__global__ void scanC_kernel() {
    int i = blockIdx.x * 1024 + threadIdx.x;
    if (i < N_NODES) {
        int off = g_boff[blockIdx.x];
        int r = g_rowptr[i + 1] + off;
        g_rowptr[i + 1] = r;
        g_wofs[i] = r - g_cnt[i];
    }
}

__global__ void scatter_kernel(const float* __restrict__ ea) {
    int w = (blockIdx.x * blockDim.x + threadIdx.x) >> 5;
    int lane = threadIdx.x & 31;
    if (w >= N_EDGES) return;
    int pos = 0;
    if (lane == 0) {
        int d = g_dst[w];
        pos = atomicAdd(&g_wofs[d], 1);
        g_esrc[pos] = g_src[w];
    }
    pos = __shfl_sync(0xffffffffu, pos, 0);
    g_ea[(size_t)pos * 32 + lane] = ea[(size_t)w * 32 + lane];
}

// ---------------- hi/lo bf16 split ----------------
__device__ __forceinline__ void splitf(float x, __nv_bfloat16& hi, __nv_bfloat16& lo) {
    hi = __float2bfloat16(x);
    lo = __float2bfloat16(x - __bfloat162float(hi));
}

// activations: X[M,K] fp32 -> Ahl[M,2K] bf16 (hi cols [0,K), lo cols [K,2K))
__global__ void cvt_kernel(const float* __restrict__ X, int M, int K) {
    int i = blockIdx.x * 256 + threadIdx.x;
    if (i >= M * K) return;
    int r = i / K, c = i % K;
    __nv_bfloat16 hi, lo;
    splitf(X[i], hi, lo);
    g_Ahl[(size_t)r * 2 * K + c] = hi;
    g_Ahl[(size_t)r * 2 * K + K + c] = lo;
}

// ---------------- composite weights: Wqe = Wq @ We^T, bqe = bq @ We^T ----------------
__global__ void compose_kernel(const float* __restrict__ Wq, const float* __restrict__ bq,
                               const float* __restrict__ We, int K, int D) {
    int idx = blockIdx.x * 256 + threadIdx.x;
    if (idx < K * 32) {
        int kk = idx >> 5, n = idx & 31;
        float s = 0.f;
        for (int j = 0; j < D; j++) s = fmaf(Wq[kk * D + j], We[n * D + j], s);
        g_Wqe[idx] = s;
    }
    if (idx < 32) {
        float s = 0.f;
        for (int j = 0; j < D; j++) s = fmaf(bq[j], We[idx * D + j], s);
        g_bqe[idx] = s;
    }
}

// ---------------- weight prep: WT[NT][2K] bf16 (hi|lo), ball[NT] ----------------
__global__ void wprep_kernel(const float* __restrict__ Wq, const float* __restrict__ Wk,
                             const float* __restrict__ Wv, const float* __restrict__ Ws,
                             const float* __restrict__ bq, const float* __restrict__ bk,
                             const float* __restrict__ bv, const float* __restrict__ bs,
                             int K, int D, int NT) {
    int idx = blockIdx.x * 256 + threadIdx.x;
    if (idx >= NT * K) return;
    int n = idx / K, kk = idx % K;
    float w;
    if (n < D)            w = Wq[kk * D + n];
    else if (n < 2 * D)   w = Wk[kk * D + (n - D)];
    else if (n < 3 * D)   w = Wv[kk * D + (n - 2 * D)];
    else if (n < 4 * D)   w = Ws[kk * D + (n - 3 * D)];
    else                  w = g_Wqe[kk * 32 + (n - 4 * D)];
    __nv_bfloat16 hi, lo;
    splitf(w, hi, lo);
    g_WT[(size_t)n * 2 * K + kk] = hi;
    g_WT[(size_t)n * 2 * K + K + kk] = lo;
    if (kk == 0) {
        float b;
        if (n < D)          b = bq[n];
        else if (n < 2 * D) b = bk[n - D];
        else if (n < 3 * D) b = bv[n - 2 * D];
        else if (n < 4 * D) b = bs[n - 3 * D];
        else                b = g_bqe[n - 4 * D];
        g_ball[n] = b;
    }
}

// ---------------- HMMA GEMM with split epilogue routing ----------------
// out cols: [0,D) -> qse q ; [D,3D) -> kv (k|v) ; [3D,NT) -> qse skip|qE (col-2D)
#define APAD 72
__global__ __launch_bounds__(256) void gemm_mma(int M, int K, int NT, int D) {
    __shared__ __align__(16) __nv_bfloat16 As[2][128][APAD];
    __shared__ __align__(16) __nv_bfloat16 Bs[2][64][APAD];
    int tid = threadIdx.x, lane = tid & 31, wid = tid >> 5;
    int warp_m = wid & 3, warp_n = wid >> 2;
    int m0 = blockIdx.x * 128, n0 = blockIdx.y * 64;
    int K2 = 2 * K;
    int NC = 3 * K / 64;
    int QW = 2 * D + 32, KW = 2 * D;

    const __nv_bfloat16* Ahl = g_Ahl;
    const __nv_bfloat16* WT = g_WT;

    float cfr[2][4][4];
    #pragma unroll
    for (int mt = 0; mt < 2; mt++)
        #pragma unroll
        for (int nt = 0; nt < 4; nt++)
            #pragma unroll
            for (int j = 0; j < 4; j++) cfr[mt][nt][j] = 0.f;

    auto stage = [&](int c, int buf) {
        int kp = c * 64;
        int ac = (kp < K) ? kp : kp - K;          // A: [hi | hi | lo]
        int bc = (kp < 2 * K) ? kp : kp - 2 * K;  // B: [hi | lo | hi]
        #pragma unroll
        for (int f = tid; f < 1024; f += 256) {
            int r = f >> 3, c16 = f & 7;
            int gr = m0 + r;
            if (gr < M)
                __pipeline_memcpy_async(&As[buf][r][c16 * 8],
                                        &Ahl[(size_t)gr * K2 + ac + c16 * 8], 16);
        }
        #pragma unroll
        for (int f = tid; f < 512; f += 256) {
            int r = f >> 3, c16 = f & 7;
            int n = n0 + r;
            if (n < NT)
                __pipeline_memcpy_async(&Bs[buf][r][c16 * 8],
                                        &WT[(size_t)n * K2 + bc + c16 * 8], 16);
        }
        __pipeline_commit();
    };

    stage(0, 0);

    for (int c = 0; c < NC; c++) {
        int buf = c & 1;
        bool more = (c + 1 < NC);
        if (more) stage(c + 1, buf ^ 1);
        __pipeline_wait_prior(more ? 1 : 0);
        __syncthreads();

        uint32_t sA = smem_to_u32(&As[buf][0][0]);
        uint32_t sB = smem_to_u32(&Bs[buf][0][0]);
        #pragma unroll
        for (int kk = 0; kk < 64; kk += 16) {
            uint32_t afr[2][4], bfr[2][4];
            #pragma unroll
            for (int mt = 0; mt < 2; mt++) {
                int row = warp_m * 32 + mt * 16 + (lane & 15);
                int koff = kk + ((lane >> 4) << 3);
                ldsm4(afr[mt], sA + row * (APAD * 2) + koff * 2);
            }
            #pragma unroll
            for (int ntp = 0; ntp < 2; ntp++) {
                int nrow = warp_n * 32 + ntp * 16 + ((lane >> 4) << 3) + (lane & 7);
                int koff = kk + (((lane >> 3) & 1) << 3);
                ldsm4(bfr[ntp], sB + nrow * (APAD * 2) + koff * 2);
            }
            #pragma unroll
            for (int mt = 0; mt < 2; mt++)
                #pragma unroll
                for (int nt = 0; nt < 4; nt++)
                    mma16816(cfr[mt][nt], afr[mt], &bfr[nt >> 1][(nt & 1) * 2]);
        }
        __syncthreads();
    }

    // epilogue with column routing
    int g = lane >> 2, t4 = lane & 3;
    #pragma unroll
    for (int mt = 0; mt < 2; mt++) {
        #pragma unroll
        for (int nt = 0; nt < 4; nt++) {
            int col = n0 + warp_n * 32 + nt * 8 + t4 * 2;
            if (col >= NT) continue;
            float2 bb = *(const float2*)&g_ball[col];
            float* dst; int wdt; int c2;
            if (col < D)          { dst = g_qse; wdt = QW; c2 = col; }
            else if (col < 3 * D) { dst = g_kv;  wdt = KW; c2 = col - D; }
            else                  { dst = g_qse; wdt = QW; c2 = col - 2 * D; }
            int r0 = m0 + warp_m * 32 + mt * 16 + g;
            if (r0 < M) {
                float2 o = make_float2(cfr[mt][nt][0] + bb.x, cfr[mt][nt][1] + bb.y);
                *(float2*)&dst[(size_t)r0 * wdt + c2] = o;
            }
            int r1 = r0 + 8;
            if (r1 < M) {
                float2 o = make_float2(cfr[mt][nt][2] + bb.x, cfr[mt][nt][3] + bb.y);
                *(float2*)&dst[(size_t)r1 * wdt + c2] = o;
            }
        }
    }
}

// ---------------- attention: fused, compact kv gather ----------------
template <int DOUT>
__global__ void attn_kernel(const float* __restrict__ qse, const float* __restrict__ kv,
                            float* __restrict__ h, float* __restrict__ aw) {
    constexpr int QW = 2 * DOUT + 32, KW = 2 * DOUT;
    int w = (blockIdx.x * blockDim.x + threadIdx.x) >> 5;
    if (w >= N_NODES) return;
    int lane = threadIdx.x & 31;
    constexpr int VEC = DOUT / 32;
    float qr[VEC], acc[VEC];
    {
        const float* qp = qse + (size_t)w * QW + lane * VEC;
        #pragma unroll
        for (int j = 0; j < VEC; j++) { qr[j] = qp[j]; acc[j] = 0.f; }
    }
    float qe_l = qse[(size_t)w * QW + 2 * DOUT + lane];
    float m = -__int_as_float(0x7f800000);
    float s = 0.f, accw = 0.f;
    int beg = g_rowptr[w], end = g_rowptr[w + 1];
    const float scale = rsqrtf((float)DOUT);

    float kc[VEC], vc[VEC], eac = 0.f;
    if (beg < end) {
        int src = g_esrc[beg];
        eac = g_ea[(size_t)beg * 32 + lane];
        const float* kp = kv + (size_t)src * KW + lane * VEC;
        const float* vp = kv + (size_t)src * KW + DOUT + lane * VEC;
        if constexpr (VEC == 4) {
            float4 kt = *(const float4*)kp; float4 vt = *(const float4*)vp;
            kc[0] = kt.x; kc[1] = kt.y; kc[2] = kt.z; kc[3] = kt.w;
            vc[0] = vt.x; vc[1] = vt.y; vc[2] = vt.z; vc[3] = vt.w;
        } else if constexpr (VEC == 2) {
            float2 kt = *(const float2*)kp; float2 vt = *(const float2*)vp;
            kc[0] = kt.x; kc[1] = kt.y; vc[0] = vt.x; vc[1] = vt.y;
        } else { kc[0] = kp[0]; vc[0] = vp[0]; }
    }
    for (int i = beg; i < end; i++) {
        float eav = eac;
        float kvr[VEC], vv[VEC];
        #pragma unroll
        for (int j = 0; j < VEC; j++) { kvr[j] = kc[j]; vv[j] = vc[j]; }
        if (i + 1 < end) {
            int src = g_esrc[i + 1];
            eac = g_ea[(size_t)(i + 1) * 32 + lane];
            const float* kp = kv + (size_t)src * KW + lane * VEC;
            const float* vp = kv + (size_t)src * KW + DOUT + lane * VEC;
            if constexpr (VEC == 4) {
                float4 kt = *(const float4*)kp; float4 vt = *(const float4*)vp;
                kc[0] = kt.x; kc[1] = kt.y; kc[2] = kt.z; kc[3] = kt.w;
                vc[0] = vt.x; vc[1] = vt.y; vc[2] = vt.z; vc[3] = vt.w;
            } else if constexpr (VEC == 2) {
                float2 kt = *(const float2*)kp; float2 vt = *(const float2*)vp;
                kc[0] = kt.x; kc[1] = kt.y; vc[0] = vt.x; vc[1] = vt.y;
            } else { kc[0] = kp[0]; vc[0] = vp[0]; }
        }
        float dot = qe_l * eav;
        #pragma unroll
        for (int j = 0; j < VEC; j++) dot = fmaf(qr[j], kvr[j], dot);
        #pragma unroll
        for (int off = 16; off; off >>= 1) dot += __shfl_xor_sync(0xffffffffu, dot, off);
        float alpha = dot * scale;
        float nm = fmaxf(m, alpha);
        float corr = __expf(m - nm);
        float wgt = __expf(alpha - nm);
        s = s * corr + wgt;
        accw = accw * corr + wgt * eav;
        #pragma unroll
        for (int j = 0; j < VEC; j++) acc[j] = fmaf(wgt, vv[j], acc[j] * corr);
        m = nm;
    }
    float inv = (s > 0.f) ? 1.f / s : 0.f;
    const float* sp = qse + (size_t)w * QW + DOUT + lane * VEC;
    float* hp = h + (size_t)w * DOUT + lane * VEC;
    #pragma unroll
    for (int j = 0; j < VEC; j++) hp[j] = sp[j] + acc[j] * inv;
    aw[(size_t)w * 32 + lane] = accw * inv;
}

// ---------------- agg fuse: H = relu(H + AW @ We); also writes bf16 hi/lo split ----------------
template <int BN>
__global__ __launch_bounds__(256) void aggfuse(const float* __restrict__ AW,
                                               const float* __restrict__ We,
                                               float* H, int M) {
    constexpr int BM = 128, BK = 32;
    constexpr int TN = BN / 16, TM = 8, NH = TN / 2;
    __shared__ float As[BK][BM + 4];
    __shared__ float Ws[BK][BN];
    int tid = threadIdx.x;
    int ct = tid & 15, rt = tid >> 4;
    int row0 = blockIdx.x * BM;

    #pragma unroll
    for (int it = 0; it < 4; it++) {
        int f = tid + 256 * it;
        int r = f >> 3, kq = f & 7;
        int gr = row0 + r;
        float4 a = make_float4(0.f, 0.f, 0.f, 0.f);
        if (gr < M) a = *(const float4*)&AW[(size_t)gr * 32 + kq * 4];
        As[kq * 4 + 0][r] = a.x;
        As[kq * 4 + 1][r] = a.y;
        As[kq * 4 + 2][r] = a.z;
        As[kq * 4 + 3][r] = a.w;
    }
    #pragma unroll
    for (int f = tid; f < 8 * BN; f += 256) {
        int kk = f / (BN / 4), n4 = f % (BN / 4);
        *(float4*)&Ws[kk][n4 * 4] = *(const float4*)&We[(size_t)kk * BN + n4 * 4];
    }
    __syncthreads();

    unsigned long long acc[TM][NH];
    #pragma unroll
    for (int t = 0; t < TM; t++)
        #pragma unroll
        for (int n = 0; n < NH; n++) acc[t][n] = 0ull;

    #pragma unroll
    for (int kk = 0; kk < BK; kk++) {
        float4 a0 = *(const float4*)&As[kk][rt * 8];
        float4 a1 = *(const float4*)&As[kk][rt * 8 + 4];
        float av[8] = {a0.x, a0.y, a0.z, a0.w, a1.x, a1.y, a1.z, a1.w};
        unsigned long long b2[NH];
        const float* wp = &Ws[kk][ct * TN];
        if constexpr (NH == 4) {
            ulonglong2 p0 = ((const ulonglong2*)wp)[0];
            ulonglong2 p1 = ((const ulonglong2*)wp)[1];
            b2[0] = p0.x; b2[1] = p0.y; b2[2] = p1.x; b2[3] = p1.y;
        } else if constexpr (NH == 2) {
            ulonglong2 p0 = ((const ulonglong2*)wp)[0];
            b2[0] = p0.x; b2[1] = p0.y;
        } else {
            b2[0] = *(const unsigned long long*)wp;
        }
        #pragma unroll
        for (int t = 0; t < TM; t++) {
            unsigned long long a2 = pk2(av[t], av[t]);
            #pragma unroll
            for (int n = 0; n < NH; n++) acc[t][n] = fma2(a2, b2[n], acc[t][n]);
        }
    }
    #pragma unroll
    for (int t = 0; t < TM; t++) {
        int r = row0 + rt * 8 + t;
        if (r < M) {
            #pragma unroll
            for (int n = 0; n < NH; n++) {
                float x, y; upk2(acc[t][n], x, y);
                float2 hprev = *(const float2*)&H[(size_t)r * BN + ct * TN + 2 * n];
                float2 o = make_float2(fmaxf(hprev.x + x, 0.f), fmaxf(hprev.y + y, 0.f));
                *(float2*)&H[(size_t)r * BN + ct * TN + 2 * n] = o;
                // fused hi/lo bf16 split for next layer's GEMM input
                int col = ct * TN + 2 * n;
                __nv_bfloat16 hx, lx, hy, ly;
                splitf(o.x, hx, lx);
                splitf(o.y, hy, ly);
                __nv_bfloat162* hi2 = (__nv_bfloat162*)&g_Ahl[(size_t)r * 2 * BN + col];
                __nv_bfloat162* lo2 = (__nv_bfloat162*)&g_Ahl[(size_t)r * 2 * BN + BN + col];
                *hi2 = __nv_bfloat162(hx, hy);
                *lo2 = __nv_bfloat162(lx, ly);
            }
        }
    }
}

// ---------------- final linear ----------------
__global__ void final_kernel(const float* __restrict__ h, const float* __restrict__ Wc,
                             const float* __restrict__ bc, float* __restrict__ out) {
    int i = blockIdx.x * blockDim.x + threadIdx.x;
    if (i >= N_NODES) return;
    float s = bc[0];
    #pragma unroll
    for (int c = 0; c < 32; c++) s = fmaf(h[(size_t)i * 32 + c], __ldg(&Wc[c]), s);
    out[i] = s;
}

// ---------------- host driver ----------------
extern "C" void kernel_launch(void* const* d_in, const int* in_sizes, int n_in,
                              void* d_out, int out_size) {
    const float* x  = (const float*)d_in[0];
    const void*  ei = d_in[1];
    const float* ea = (const float*)d_in[2];
    const float* W[3][9];
    int p = 3;
    for (int l = 0; l < 3; l++)
        for (int j = 0; j < 9; j++) W[l][j] = (const float*)d_in[p++];
    const float* Wc = (const float*)d_in[30];
    const float* bc = (const float*)d_in[31];

    float *hA, *hB, *awb, *qseb, *kvb;
    cudaGetSymbolAddress((void**)&hA,   g_hA);
    cudaGetSymbolAddress((void**)&hB,   g_hB);
    cudaGetSymbolAddress((void**)&awb,  g_aw);
    cudaGetSymbolAddress((void**)&qseb, g_qse);
    cudaGetSymbolAddress((void**)&kvb,  g_kv);

    int din[3]  = {128, 128, 64};
    int dout[3] = {128, 64, 32};
    float* houts[3] = {hA, hB, hA};
    dim3 ngrid((N_NODES * 32 + 255) / 256);
    int gx = (N_NODES + 127) / 128;

    // ---- Layer-1 GEMM path first (independent of graph preprocessing);
    // gemm_mma is launch #4 for the profiler.
    cvt_kernel<<<(N_NODES * 128 + 255) / 256, 256>>>(x, N_NODES, 128);
    compose_kernel<<<(128 * 32 + 255) / 256, 256>>>(W[0][0], W[0][1], W[0][6], 128, 128);
    wprep_kernel<<<(544 * 128 + 255) / 256, 256>>>(W[0][0], W[0][2], W[0][4], W[0][7],
                                                   W[0][1], W[0][3], W[0][5], W[0][8],
                                                   128, 128, 544);
    gemm_mma<<<dim3(M_TILES, 9), 256>>>(N_NODES, 128, 544, 128);

    // ---- graph preprocessing
    detect_kernel<<<1, 256>>>(ei);
    convert_kernel<<<(N_EDGES + 255) / 256, 256>>>(ei);
    hist_kernel<<<(N_EDGES + 255) / 256, 256>>>();
    int NB = (N_NODES + 1023) / 1024;
    scanA_kernel<<<NB, 1024>>>();
    scanB_kernel<<<1, 64>>>(NB);
    scanC_kernel<<<NB, 1024>>>();
    scatter_kernel<<<(N_EDGES * 32 + 255) / 256, 256>>>(ea);

    for (int l = 0; l < 3; l++) {
        int K = din[l], D = dout[l];
        int NT = 4 * D + 32;
        float* hout = houts[l];
        if (l > 0) {
            compose_kernel<<<(K * 32 + 255) / 256, 256>>>(W[l][0], W[l][1], W[l][6], K, D);
            wprep_kernel<<<(NT * K + 255) / 256, 256>>>(W[l][0], W[l][2], W[l][4], W[l][7],
                                                        W[l][1], W[l][3], W[l][5], W[l][8],
                                                        K, D, NT);
            int ntiles = (NT + 63) / 64;
            gemm_mma<<<dim3(M_TILES, ntiles), 256>>>(N_NODES, K, NT, D);
        }
        if (D == 128)      attn_kernel<128><<<ngrid, 256>>>(qseb, kvb, hout, awb);
        else if (D == 64)  attn_kernel<64><<<ngrid, 256>>>(qseb, kvb, hout, awb);
        else               attn_kernel<32><<<ngrid, 256>>>(qseb, kvb, hout, awb);
        if (D == 128)      aggfuse<128><<<gx, 256>>>(awb, W[l][6], hout, N_NODES);
        else if (D == 64)  aggfuse<64><<<gx, 256>>>(awb, W[l][6], hout, N_NODES);
        else               aggfuse<32><<<gx, 256>>>(awb, W[l][6], hout, N_NODES);
    }
    final_kernel<<<(N_NODES + 255) / 256, 256>>>(hA, Wc, bc, (float*)d_out);
}

// round 17
// speedup vs baseline: 1.1331x; 1.0654x over previous
#include <cuda_runtime.h>
#include <cuda_pipeline.h>
#include <cuda_bf16.h>
#include <cstdint>

#define N_NODES 50000
#define N_EDGES 800000
#define M_TILES 391   // ceil(50000/128)

// ---------------- static device scratch ----------------
__device__ float g_qse[(size_t)N_NODES * 288];         // q|skip|qE rows (2D+32)
__device__ float g_kv[(size_t)N_NODES * 256];          // k|v rows (2D) -- the ONLY gathered tensor
__device__ __nv_bfloat16 g_Ahl[(size_t)N_NODES * 256]; // activations hi|lo (bf16)
__device__ __nv_bfloat16 g_WT[544 * 256];              // W~^T per layer: [NT][2K] hi|lo
__device__ float g_ball[544];                          // concat bias per layer
__device__ float g_hA[(size_t)N_NODES * 128];
__device__ float g_hB[(size_t)N_NODES * 128];
__device__ float g_aw[(size_t)N_NODES * 32];
__device__ float g_ea[(size_t)N_EDGES * 32];
__device__ float g_Wqe[128 * 32];
__device__ float g_bqe[32];
__device__ int   g_src[N_EDGES];
__device__ int   g_dst[N_EDGES];
__device__ int   g_esrc[N_EDGES];
__device__ int   g_rowptr[N_NODES + 1];
__device__ int   g_cnt[N_NODES];
__device__ int   g_wofs[N_NODES];
__device__ int   g_bsum[64];
__device__ int   g_boff[64];
__device__ int   g_flag[1];

// ---------------- packed fp32x2 helpers ----------------
__device__ __forceinline__ unsigned long long pk2(float x, float y) {
    unsigned long long r;
    asm("mov.b64 %0, {%1,%2};" : "=l"(r) : "f"(x), "f"(y));
    return r;
}
__device__ __forceinline__ void upk2(unsigned long long p, float& x, float& y) {
    asm("mov.b64 {%0,%1}, %2;" : "=f"(x), "=f"(y) : "l"(p));
}
__device__ __forceinline__ unsigned long long fma2(unsigned long long a, unsigned long long b,
                                                   unsigned long long c) {
    unsigned long long d;
    asm("fma.rn.f32x2 %0, %1, %2, %3;" : "=l"(d) : "l"(a), "l"(b), "l"(c));
    return d;
}

__device__ __forceinline__ uint32_t smem_to_u32(const void* p) {
    uint32_t a;
    asm("{ .reg .u64 t; cvta.to.shared.u64 t, %1; cvt.u32.u64 %0, t; }" : "=r"(a) : "l"(p));
    return a;
}

// ---------------- HMMA helpers (baseline PTX, sm_80+) ----------------
__device__ __forceinline__ void ldsm4(uint32_t* r, uint32_t addr) {
    asm volatile("ldmatrix.sync.aligned.m8n8.x4.shared.b16 {%0,%1,%2,%3}, [%4];"
                 : "=r"(r[0]), "=r"(r[1]), "=r"(r[2]), "=r"(r[3]) : "r"(addr));
}
__device__ __forceinline__ void mma16816(float* c, const uint32_t* a, const uint32_t* b) {
    asm volatile("mma.sync.aligned.m16n8k16.row.col.f32.bf16.bf16.f32 "
                 "{%0,%1,%2,%3}, {%4,%5,%6,%7}, {%8,%9}, {%0,%1,%2,%3};"
                 : "+f"(c[0]), "+f"(c[1]), "+f"(c[2]), "+f"(c[3])
                 : "r"(a[0]), "r"(a[1]), "r"(a[2]), "r"(a[3]), "r"(b[0]), "r"(b[1]));
}

// ---------------- edge_index dtype detection ----------------
__global__ void detect_kernel(const void* ei) {
    __shared__ int ok;
    if (threadIdx.x == 0) ok = 1;
    __syncthreads();
    const long long* p = (const long long*)ei;
    long long v = p[threadIdx.x];
    if (!(v >= 0 && v < (long long)N_NODES)) atomicExch(&ok, 0);
    __syncthreads();
    if (threadIdx.x == 0) g_flag[0] = ok;
}

__global__ void convert_kernel(const void* ei) {
    int i = blockIdx.x * blockDim.x + threadIdx.x;
    int is64 = g_flag[0];
    if (i < N_EDGES) {
        int s, d;
        if (is64) {
            const long long* p = (const long long*)ei;
            s = (int)p[i]; d = (int)p[N_EDGES + i];
        } else {
            const int* p = (const int*)ei;
            s = p[i]; d = p[N_EDGES + i];
        }
        g_src[i] = s; g_dst[i] = d;
    }
    if (i < N_NODES) g_cnt[i] = 0;
}

__global__ void hist_kernel() {
    int i = blockIdx.x * blockDim.x + threadIdx.x;
    if (i < N_EDGES) atomicAdd(&g_cnt[g_dst[i]], 1);
}

__global__ void scanA_kernel() {
    __shared__ int wsum[32];
    int tid = threadIdx.x, lane = tid & 31, wid = tid >> 5;
    int i = blockIdx.x * 1024 + tid;
    int v = (i < N_NODES) ? g_cnt[i] : 0;
    int x = v;
    #pragma unroll
    for (int off = 1; off < 32; off <<= 1) {
        int t = __shfl_up_sync(0xffffffffu, x, off);
        if (lane >= off) x += t;
    }
    if (lane == 31) wsum[wid] = x;
    __syncthreads();
    if (wid == 0) {
        int y = wsum[lane];
        #pragma unroll
        for (int off = 1; off < 32; off <<= 1) {
            int t = __shfl_up_sync(0xffffffffu, y, off);
            if (lane >= off) y += t;
        }
        wsum[lane] = y;
    }
    __syncthreads();
    int incl = x + (wid ? wsum[wid - 1] : 0);
    if (i < N_NODES) g_rowptr[i + 1] = incl;
    if (tid == 1023) g_bsum[blockIdx.x] = incl;
}

__global__ void scanB_kernel(int nb) {
    __shared__ int w0tot;
    int tid = threadIdx.x, lane = tid & 31, wid = tid >> 5;
    int v = (tid < nb) ? g_bsum[tid] : 0;
    int x = v;
    #pragma unroll
    for (int off = 1; off < 32; off <<= 1) {
        int t = __shfl_up_sync(0xffffffffu, x, off);
        if (lane >= off) x += t;
    }
    if (wid == 0 && lane == 31) w0tot = x;
    __syncthreads();
    int incl = x + (wid ? w0tot : 0);
    g_boff[tid] = incl - v;
    if (tid == 0) g_rowptr[0] = 0;
}

__global__ void scanC_kernel() {
    int i = blockIdx.x * 1024 + threadIdx.x;
    if (i < N_NODES) {
        int off = g_boff[blockIdx.x];
        int r = g_rowptr[i + 1] + off;
        g_rowptr[i + 1] = r;
        g_wofs[i] = r - g_cnt[i];
    }
}

__global__ void scatter_kernel(const float* __restrict__ ea) {
    int w = (blockIdx.x * blockDim.x + threadIdx.x) >> 5;
    int lane = threadIdx.x & 31;
    if (w >= N_EDGES) return;
    int pos = 0;
    if (lane == 0) {
        int d = g_dst[w];
        pos = atomicAdd(&g_wofs[d], 1);
        g_esrc[pos] = g_src[w];
    }
    pos = __shfl_sync(0xffffffffu, pos, 0);
    g_ea[(size_t)pos * 32 + lane] = ea[(size_t)w * 32 + lane];
}

// ---------------- hi/lo bf16 split ----------------
__device__ __forceinline__ void splitf(float x, __nv_bfloat16& hi, __nv_bfloat16& lo) {
    hi = __float2bfloat16(x);
    lo = __float2bfloat16(x - __bfloat162float(hi));
}

// activations: X[M,K] fp32 -> Ahl[M,2K] bf16 (hi cols [0,K), lo cols [K,2K))
__global__ void cvt_kernel(const float* __restrict__ X, int M, int K) {
    int i = blockIdx.x * 256 + threadIdx.x;
    if (i >= M * K) return;
    int r = i / K, c = i % K;
    __nv_bfloat16 hi, lo;
    splitf(X[i], hi, lo);
    g_Ahl[(size_t)r * 2 * K + c] = hi;
    g_Ahl[(size_t)r * 2 * K + K + c] = lo;
}

// ---------------- composite weights: Wqe = Wq @ We^T, bqe = bq @ We^T ----------------
__global__ void compose_kernel(const float* __restrict__ Wq, const float* __restrict__ bq,
                               const float* __restrict__ We, int K, int D) {
    int idx = blockIdx.x * 256 + threadIdx.x;
    if (idx < K * 32) {
        int kk = idx >> 5, n = idx & 31;
        float s = 0.f;
        for (int j = 0; j < D; j++) s = fmaf(Wq[kk * D + j], We[n * D + j], s);
        g_Wqe[idx] = s;
    }
    if (idx < 32) {
        float s = 0.f;
        for (int j = 0; j < D; j++) s = fmaf(bq[j], We[idx * D + j], s);
        g_bqe[idx] = s;
    }
}

// ---------------- weight prep: WT[NT][2K] bf16 (hi|lo), ball[NT] ----------------
__global__ void wprep_kernel(const float* __restrict__ Wq, const float* __restrict__ Wk,
                             const float* __restrict__ Wv, const float* __restrict__ Ws,
                             const float* __restrict__ bq, const float* __restrict__ bk,
                             const float* __restrict__ bv, const float* __restrict__ bs,
                             int K, int D, int NT) {
    int idx = blockIdx.x * 256 + threadIdx.x;
    if (idx >= NT * K) return;
    int n = idx / K, kk = idx % K;
    float w;
    if (n < D)            w = Wq[kk * D + n];
    else if (n < 2 * D)   w = Wk[kk * D + (n - D)];
    else if (n < 3 * D)   w = Wv[kk * D + (n - 2 * D)];
    else if (n < 4 * D)   w = Ws[kk * D + (n - 3 * D)];
    else                  w = g_Wqe[kk * 32 + (n - 4 * D)];
    __nv_bfloat16 hi, lo;
    splitf(w, hi, lo);
    g_WT[(size_t)n * 2 * K + kk] = hi;
    g_WT[(size_t)n * 2 * K + K + kk] = lo;
    if (kk == 0) {
        float b;
        if (n < D)          b = bq[n];
        else if (n < 2 * D) b = bk[n - D];
        else if (n < 3 * D) b = bv[n - 2 * D];
        else if (n < 4 * D) b = bs[n - 3 * D];
        else                b = g_bqe[n - 4 * D];
        g_ball[n] = b;
    }
}

// ---------------- HMMA GEMM with split epilogue routing ----------------
// out cols: [0,D) -> qse q ; [D,3D) -> kv (k|v) ; [3D,NT) -> qse skip|qE (col-2D)
#define APAD 72
__global__ __launch_bounds__(256) void gemm_mma(int M, int K, int NT, int D) {
    __shared__ __align__(16) __nv_bfloat16 As[2][128][APAD];
    __shared__ __align__(16) __nv_bfloat16 Bs[2][64][APAD];
    int tid = threadIdx.x, lane = tid & 31, wid = tid >> 5;
    int warp_m = wid & 3, warp_n = wid >> 2;
    int m0 = blockIdx.x * 128, n0 = blockIdx.y * 64;
    int K2 = 2 * K;
    int NC = 3 * K / 64;
    int QW = 2 * D + 32, KW = 2 * D;

    const __nv_bfloat16* Ahl = g_Ahl;
    const __nv_bfloat16* WT = g_WT;

    float cfr[2][4][4];
    #pragma unroll
    for (int mt = 0; mt < 2; mt++)
        #pragma unroll
        for (int nt = 0; nt < 4; nt++)
            #pragma unroll
            for (int j = 0; j < 4; j++) cfr[mt][nt][j] = 0.f;

    auto stage = [&](int c, int buf) {
        int kp = c * 64;
        int ac = (kp < K) ? kp : kp - K;          // A: [hi | hi | lo]
        int bc = (kp < 2 * K) ? kp : kp - 2 * K;  // B: [hi | lo | hi]
        #pragma unroll
        for (int f = tid; f < 1024; f += 256) {
            int r = f >> 3, c16 = f & 7;
            int gr = m0 + r;
            if (gr < M)
                __pipeline_memcpy_async(&As[buf][r][c16 * 8],
                                        &Ahl[(size_t)gr * K2 + ac + c16 * 8], 16);
        }
        #pragma unroll
        for (int f = tid; f < 512; f += 256) {
            int r = f >> 3, c16 = f & 7;
            int n = n0 + r;
            if (n < NT)
                __pipeline_memcpy_async(&Bs[buf][r][c16 * 8],
                                        &WT[(size_t)n * K2 + bc + c16 * 8], 16);
        }
        __pipeline_commit();
    };

    stage(0, 0);

    for (int c = 0; c < NC; c++) {
        int buf = c & 1;
        bool more = (c + 1 < NC);
        if (more) stage(c + 1, buf ^ 1);
        __pipeline_wait_prior(more ? 1 : 0);
        __syncthreads();

        uint32_t sA = smem_to_u32(&As[buf][0][0]);
        uint32_t sB = smem_to_u32(&Bs[buf][0][0]);
        #pragma unroll
        for (int kk = 0; kk < 64; kk += 16) {
            uint32_t afr[2][4], bfr[2][4];
            #pragma unroll
            for (int mt = 0; mt < 2; mt++) {
                int row = warp_m * 32 + mt * 16 + (lane & 15);
                int koff = kk + ((lane >> 4) << 3);
                ldsm4(afr[mt], sA + row * (APAD * 2) + koff * 2);
            }
            #pragma unroll
            for (int ntp = 0; ntp < 2; ntp++) {
                int nrow = warp_n * 32 + ntp * 16 + ((lane >> 4) << 3) + (lane & 7);
                int koff = kk + (((lane >> 3) & 1) << 3);
                ldsm4(bfr[ntp], sB + nrow * (APAD * 2) + koff * 2);
            }
            #pragma unroll
            for (int mt = 0; mt < 2; mt++)
                #pragma unroll
                for (int nt = 0; nt < 4; nt++)
                    mma16816(cfr[mt][nt], afr[mt], &bfr[nt >> 1][(nt & 1) * 2]);
        }
        __syncthreads();
    }

    // epilogue with column routing
    int g = lane >> 2, t4 = lane & 3;
    #pragma unroll
    for (int mt = 0; mt < 2; mt++) {
        #pragma unroll
        for (int nt = 0; nt < 4; nt++) {
            int col = n0 + warp_n * 32 + nt * 8 + t4 * 2;
            if (col >= NT) continue;
            float2 bb = *(const float2*)&g_ball[col];
            float* dst; int wdt; int c2;
            if (col < D)          { dst = g_qse; wdt = QW; c2 = col; }
            else if (col < 3 * D) { dst = g_kv;  wdt = KW; c2 = col - D; }
            else                  { dst = g_qse; wdt = QW; c2 = col - 2 * D; }
            int r0 = m0 + warp_m * 32 + mt * 16 + g;
            if (r0 < M) {
                float2 o = make_float2(cfr[mt][nt][0] + bb.x, cfr[mt][nt][1] + bb.y);
                *(float2*)&dst[(size_t)r0 * wdt + c2] = o;
            }
            int r1 = r0 + 8;
            if (r1 < M) {
                float2 o = make_float2(cfr[mt][nt][2] + bb.x, cfr[mt][nt][3] + bb.y);
                *(float2*)&dst[(size_t)r1 * wdt + c2] = o;
            }
        }
    }
}

// ---------------- attention: dual-stream online softmax, compact kv gather ----------------
template <int DOUT>
__global__ void attn_kernel(const float* __restrict__ qse, const float* __restrict__ kv,
                            float* __restrict__ h, float* __restrict__ aw) {
    constexpr int QW = 2 * DOUT + 32, KW = 2 * DOUT;
    constexpr int VEC = DOUT / 32;
    int w = (blockIdx.x * blockDim.x + threadIdx.x) >> 5;
    if (w >= N_NODES) return;
    int lane = threadIdx.x & 31;
    float qr[VEC];
    {
        const float* qp = qse + (size_t)w * QW + lane * VEC;
        #pragma unroll
        for (int j = 0; j < VEC; j++) qr[j] = qp[j];
    }
    float qe_l = qse[(size_t)w * QW + 2 * DOUT + lane];
    int beg = g_rowptr[w], end = g_rowptr[w + 1];
    const float scale = rsqrtf((float)DOUT);

    float m2[2] = {-1e30f, -1e30f}, s2[2] = {0.f, 0.f}, accw[2] = {0.f, 0.f};
    float acc[2][VEC];
    #pragma unroll
    for (int p = 0; p < 2; p++)
        #pragma unroll
        for (int j = 0; j < VEC; j++) acc[p][j] = 0.f;

    float kc[2][VEC], vc[2][VEC], eac[2];
    #pragma unroll
    for (int p = 0; p < 2; p++) {
        eac[p] = 0.f;
        #pragma unroll
        for (int j = 0; j < VEC; j++) { kc[p][j] = 0.f; vc[p][j] = 0.f; }
        int i = beg + p;
        if (i < end) {
            int src = g_esrc[i];
            eac[p] = g_ea[(size_t)i * 32 + lane];
            const float* kp = kv + (size_t)src * KW + lane * VEC;
            const float* vp = kv + (size_t)src * KW + DOUT + lane * VEC;
            if constexpr (VEC == 4) {
                float4 kt = *(const float4*)kp; float4 vt = *(const float4*)vp;
                kc[p][0] = kt.x; kc[p][1] = kt.y; kc[p][2] = kt.z; kc[p][3] = kt.w;
                vc[p][0] = vt.x; vc[p][1] = vt.y; vc[p][2] = vt.z; vc[p][3] = vt.w;
            } else if constexpr (VEC == 2) {
                float2 kt = *(const float2*)kp; float2 vt = *(const float2*)vp;
                kc[p][0] = kt.x; kc[p][1] = kt.y; vc[p][0] = vt.x; vc[p][1] = vt.y;
            } else { kc[p][0] = kp[0]; vc[p][0] = vp[0]; }
        }
    }

    for (int i0 = beg; i0 < end; i0 += 2) {
        float dot[2], eav[2], vv[2][VEC];
        #pragma unroll
        for (int p = 0; p < 2; p++) {
            eav[p] = eac[p];
            #pragma unroll
            for (int j = 0; j < VEC; j++) vv[p][j] = vc[p][j];
            dot[p] = qe_l * eav[p];
            #pragma unroll
            for (int j = 0; j < VEC; j++) dot[p] = fmaf(qr[j], kc[p][j], dot[p]);
        }
        // prefetch edges i0+2, i0+3
        #pragma unroll
        for (int p = 0; p < 2; p++) {
            int nx = i0 + 2 + p;
            if (nx < end) {
                int src = g_esrc[nx];
                eac[p] = g_ea[(size_t)nx * 32 + lane];
                const float* kp = kv + (size_t)src * KW + lane * VEC;
                const float* vp = kv + (size_t)src * KW + DOUT + lane * VEC;
                if constexpr (VEC == 4) {
                    float4 kt = *(const float4*)kp; float4 vt = *(const float4*)vp;
                    kc[p][0] = kt.x; kc[p][1] = kt.y; kc[p][2] = kt.z; kc[p][3] = kt.w;
                    vc[p][0] = vt.x; vc[p][1] = vt.y; vc[p][2] = vt.z; vc[p][3] = vt.w;
                } else if constexpr (VEC == 2) {
                    float2 kt = *(const float2*)kp; float2 vt = *(const float2*)vp;
                    kc[p][0] = kt.x; kc[p][1] = kt.y; vc[p][0] = vt.x; vc[p][1] = vt.y;
                } else { kc[p][0] = kp[0]; vc[p][0] = vp[0]; }
            }
        }
        // two independent shfl-reduce chains (interleaved issue)
        #pragma unroll
        for (int off = 16; off; off >>= 1) {
            #pragma unroll
            for (int p = 0; p < 2; p++)
                dot[p] += __shfl_xor_sync(0xffffffffu, dot[p], off);
        }
        // online softmax update per stream
        #pragma unroll
        for (int p = 0; p < 2; p++) {
            if (i0 + p < end) {
                float alpha = dot[p] * scale;
                float nm = fmaxf(m2[p], alpha);
                float corr = __expf(m2[p] - nm);
                float wgt = __expf(alpha - nm);
                s2[p] = s2[p] * corr + wgt;
                accw[p] = accw[p] * corr + wgt * eav[p];
                #pragma unroll
                for (int j = 0; j < VEC; j++) acc[p][j] = fmaf(wgt, vv[p][j], acc[p][j] * corr);
                m2[p] = nm;
            }
        }
    }

    // exact merge of the two streams (-1e30 sentinel keeps empty streams NaN-free)
    float M = fmaxf(m2[0], m2[1]);
    float c0 = __expf(m2[0] - M), c1 = __expf(m2[1] - M);
    float s = s2[0] * c0 + s2[1] * c1;
    float inv = (s > 0.f) ? 1.f / s : 0.f;
    const float* sp = qse + (size_t)w * QW + DOUT + lane * VEC;
    float* hp = h + (size_t)w * DOUT + lane * VEC;
    #pragma unroll
    for (int j = 0; j < VEC; j++)
        hp[j] = sp[j] + (acc[0][j] * c0 + acc[1][j] * c1) * inv;
    aw[(size_t)w * 32 + lane] = (accw[0] * c0 + accw[1] * c1) * inv;
}

// ---------------- agg fuse: H = relu(H + AW @ We); also writes bf16 hi/lo split ----------------
template <int BN>
__global__ __launch_bounds__(256) void aggfuse(const float* __restrict__ AW,
                                               const float* __restrict__ We,
                                               float* H, int M) {
    constexpr int BM = 128, BK = 32;
    constexpr int TN = BN / 16, TM = 8, NH = TN / 2;
    __shared__ float As[BK][BM + 4];
    __shared__ float Ws[BK][BN];
    int tid = threadIdx.x;
    int ct = tid & 15, rt = tid >> 4;
    int row0 = blockIdx.x * BM;

    #pragma unroll
    for (int it = 0; it < 4; it++) {
        int f = tid + 256 * it;
        int r = f >> 3, kq = f & 7;
        int gr = row0 + r;
        float4 a = make_float4(0.f, 0.f, 0.f, 0.f);
        if (gr < M) a = *(const float4*)&AW[(size_t)gr * 32 + kq * 4];
        As[kq * 4 + 0][r] = a.x;
        As[kq * 4 + 1][r] = a.y;
        As[kq * 4 + 2][r] = a.z;
        As[kq * 4 + 3][r] = a.w;
    }
    #pragma unroll
    for (int f = tid; f < 8 * BN; f += 256) {
        int kk = f / (BN / 4), n4 = f % (BN / 4);
        *(float4*)&Ws[kk][n4 * 4] = *(const float4*)&We[(size_t)kk * BN + n4 * 4];
    }
    __syncthreads();

    unsigned long long acc[TM][NH];
    #pragma unroll
    for (int t = 0; t < TM; t++)
        #pragma unroll
        for (int n = 0; n < NH; n++) acc[t][n] = 0ull;

    #pragma unroll
    for (int kk = 0; kk < BK; kk++) {
        float4 a0 = *(const float4*)&As[kk][rt * 8];
        float4 a1 = *(const float4*)&As[kk][rt * 8 + 4];
        float av[8] = {a0.x, a0.y, a0.z, a0.w, a1.x, a1.y, a1.z, a1.w};
        unsigned long long b2[NH];
        const float* wp = &Ws[kk][ct * TN];
        if constexpr (NH == 4) {
            ulonglong2 p0 = ((const ulonglong2*)wp)[0];
            ulonglong2 p1 = ((const ulonglong2*)wp)[1];
            b2[0] = p0.x; b2[1] = p0.y; b2[2] = p1.x; b2[3] = p1.y;
        } else if constexpr (NH == 2) {
            ulonglong2 p0 = ((const ulonglong2*)wp)[0];
            b2[0] = p0.x; b2[1] = p0.y;
        } else {
            b2[0] = *(const unsigned long long*)wp;
        }
        #pragma unroll
        for (int t = 0; t < TM; t++) {
            unsigned long long a2 = pk2(av[t], av[t]);
            #pragma unroll
            for (int n = 0; n < NH; n++) acc[t][n] = fma2(a2, b2[n], acc[t][n]);
        }
    }
    #pragma unroll
    for (int t = 0; t < TM; t++) {
        int r = row0 + rt * 8 + t;
        if (r < M) {
            #pragma unroll
            for (int n = 0; n < NH; n++) {
                float x, y; upk2(acc[t][n], x, y);
                float2 hprev = *(const float2*)&H[(size_t)r * BN + ct * TN + 2 * n];
                float2 o = make_float2(fmaxf(hprev.x + x, 0.f), fmaxf(hprev.y + y, 0.f));
                *(float2*)&H[(size_t)r * BN + ct * TN + 2 * n] = o;
                // fused hi/lo bf16 split for next layer's GEMM input
                int col = ct * TN + 2 * n;
                __nv_bfloat16 hx, lx, hy, ly;
                splitf(o.x, hx, lx);
                splitf(o.y, hy, ly);
                __nv_bfloat162* hi2 = (__nv_bfloat162*)&g_Ahl[(size_t)r * 2 * BN + col];
                __nv_bfloat162* lo2 = (__nv_bfloat162*)&g_Ahl[(size_t)r * 2 * BN + BN + col];
                *hi2 = __nv_bfloat162(hx, hy);
                *lo2 = __nv_bfloat162(lx, ly);
            }
        }
    }
}

// ---------------- final linear ----------------
__global__ void final_kernel(const float* __restrict__ h, const float* __restrict__ Wc,
                             const float* __restrict__ bc, float* __restrict__ out) {
    int i = blockIdx.x * blockDim.x + threadIdx.x;
    if (i >= N_NODES) return;
    float s = bc[0];
    #pragma unroll
    for (int c = 0; c < 32; c++) s = fmaf(h[(size_t)i * 32 + c], __ldg(&Wc[c]), s);
    out[i] = s;
}

// ---------------- host driver ----------------
extern "C" void kernel_launch(void* const* d_in, const int* in_sizes, int n_in,
                              void* d_out, int out_size) {
    const float* x  = (const float*)d_in[0];
    const void*  ei = d_in[1];
    const float* ea = (const float*)d_in[2];
    const float* W[3][9];
    int p = 3;
    for (int l = 0; l < 3; l++)
        for (int j = 0; j < 9; j++) W[l][j] = (const float*)d_in[p++];
    const float* Wc = (const float*)d_in[30];
    const float* bc = (const float*)d_in[31];

    float *hA, *hB, *awb, *qseb, *kvb;
    cudaGetSymbolAddress((void**)&hA,   g_hA);
    cudaGetSymbolAddress((void**)&hB,   g_hB);
    cudaGetSymbolAddress((void**)&awb,  g_aw);
    cudaGetSymbolAddress((void**)&qseb, g_qse);
    cudaGetSymbolAddress((void**)&kvb,  g_kv);

    int din[3]  = {128, 128, 64};
    int dout[3] = {128, 64, 32};
    float* houts[3] = {hA, hB, hA};
    dim3 ngrid((N_NODES * 32 + 127) / 128);
    int gx = (N_NODES + 127) / 128;

    // ---- Layer-1 GEMM path first (independent of graph preprocessing);
    // gemm_mma is launch #4 for the profiler.
    cvt_kernel<<<(N_NODES * 128 + 255) / 256, 256>>>(x, N_NODES, 128);
    compose_kernel<<<(128 * 32 + 255) / 256, 256>>>(W[0][0], W[0][1], W[0][6], 128, 128);
    wprep_kernel<<<(544 * 128 + 255) / 256, 256>>>(W[0][0], W[0][2], W[0][4], W[0][7],
                                                   W[0][1], W[0][3], W[0][5], W[0][8],
                                                   128, 128, 544);
    gemm_mma<<<dim3(M_TILES, 9), 256>>>(N_NODES, 128, 544, 128);

    // ---- graph preprocessing
    detect_kernel<<<1, 256>>>(ei);
    convert_kernel<<<(N_EDGES + 255) / 256, 256>>>(ei);
    hist_kernel<<<(N_EDGES + 255) / 256, 256>>>();
    int NB = (N_NODES + 1023) / 1024;
    scanA_kernel<<<NB, 1024>>>();
    scanB_kernel<<<1, 64>>>(NB);
    scanC_kernel<<<NB, 1024>>>();
    scatter_kernel<<<(N_EDGES * 32 + 255) / 256, 256>>>(ea);

    for (int l = 0; l < 3; l++) {
        int K = din[l], D = dout[l];
        int NT = 4 * D + 32;
        float* hout = houts[l];
        if (l > 0) {
            compose_kernel<<<(K * 32 + 255) / 256, 256>>>(W[l][0], W[l][1], W[l][6], K, D);
            wprep_kernel<<<(NT * K + 255) / 256, 256>>>(W[l][0], W[l][2], W[l][4], W[l][7],
                                                        W[l][1], W[l][3], W[l][5], W[l][8],
                                                        K, D, NT);
            int ntiles = (NT + 63) / 64;
            gemm_mma<<<dim3(M_TILES, ntiles), 256>>>(N_NODES, K, NT, D);
        }
        if (D == 128)      attn_kernel<128><<<ngrid, 128>>>(qseb, kvb, hout, awb);
        else if (D == 64)  attn_kernel<64><<<ngrid, 128>>>(qseb, kvb, hout, awb);
        else               attn_kernel<32><<<ngrid, 128>>>(qseb, kvb, hout, awb);
        if (D == 128)      aggfuse<128><<<gx, 256>>>(awb, W[l][6], hout, N_NODES);
        else if (D == 64)  aggfuse<64><<<gx, 256>>>(awb, W[l][6], hout, N_NODES);
        else               aggfuse<32><<<gx, 256>>>(awb, W[l][6], hout, N_NODES);
    }
    final_kernel<<<(N_NODES + 255) / 256, 256>>>(hA, Wc, bc, (float*)d_out);
}